// round 15
// baseline (speedup 1.0000x reference)
#include <cuda_runtime.h>
#include <cuda_bf16.h>
#include <cuda_fp16.h>
#include <cstdint>
#include <math.h>

#define N_TOK 4096
#define DIM   1024
#define NH    16
#define HD    64

typedef unsigned long long ull;

// ===================== HMMA primitives (baseline PTX, no 'a' features) ======
__device__ __forceinline__ uint32_t smem_u32(const void* p) {
    uint32_t a;
    asm("{ .reg .u64 t; cvta.to.shared.u64 t, %1; cvt.u32.u64 %0, t; }"
        : "=r"(a) : "l"(p));
    return a;
}
__device__ __forceinline__ void ldmx4(uint32_t* r, uint32_t addr) {
    asm volatile("ldmatrix.sync.aligned.m8n8.x4.shared.b16 {%0,%1,%2,%3}, [%4];"
                 : "=r"(r[0]), "=r"(r[1]), "=r"(r[2]), "=r"(r[3]) : "r"(addr));
}
__device__ __forceinline__ void mma16816h(float* c, const uint32_t* a, const uint32_t* b) {
    asm volatile(
        "mma.sync.aligned.m16n8k16.row.col.f32.f16.f16.f32 "
        "{%0,%1,%2,%3}, {%4,%5,%6,%7}, {%8,%9}, {%0,%1,%2,%3};"
        : "+f"(c[0]), "+f"(c[1]), "+f"(c[2]), "+f"(c[3])
        : "r"(a[0]), "r"(a[1]), "r"(a[2]), "r"(a[3]), "r"(b[0]), "r"(b[1]));
}
__device__ __forceinline__ void cpa16(uint32_t dst, const void* src) {
    asm volatile("cp.async.cg.shared.global [%0], [%1], 16;"
                 :: "r"(dst), "l"(src) : "memory");
}
#define CP_COMMIT() asm volatile("cp.async.commit_group;" ::: "memory")
#define CP_WAIT(n)  asm volatile("cp.async.wait_group %0;" :: "n"(n) : "memory")

// dense GEMM smem tile: 128 rows x 32 fp16, row stride 40 (80 B)
#define TROW 40
#define TILE_ELEMS (128 * TROW)
#define GEMM_SMEM (2 * 2 * TILE_ELEMS * 2)      // 40960 B

// scores smem: Q persistent (fp16) + double-buffered K (fp16); stride 72
#define QROW 72
#define QTILE (128 * QROW)
#define SC_SMEM (3 * QTILE * 2)                  // 55296 B

// ===================== scratch globals ======================================
__device__ float g_x[N_TOK * DIM];
__device__ float g_t[N_TOK * (DIM / 2)];
__device__ float g_cw[N_TOK];
__device__ float g_relmean[N_TOK * 3];
__device__ __half g_s[(size_t)NH * N_TOK * N_TOK];  // raw scores [h][n][m], fp16

__device__ __half g_aq[N_TOK * DIM];                // A operand fp16 (reused)
__device__ __half g_qq[N_TOK * DIM];
__device__ __half g_kq[N_TOK * DIM];
__device__ __half g_vq[N_TOK * DIM];
__device__ __half g_vtb[(size_t)256 * 16 * 64 * 16]; // blocked V [mb][h][d][16m]
__device__ __half g_wq16[DIM * DIM];
__device__ __half g_wk16[DIM * DIM];
__device__ __half g_wv16[DIM * DIM];
__device__ __half g_wo16[DIM * DIM];
__device__ __half g_w116[(DIM / 2) * DIM];

// ===================== prep kernels =========================================
__global__ __launch_bounds__(256)
void cvt16(const float* __restrict__ X, __half* __restrict__ Y, int n4)
{
    const int i = blockIdx.x * blockDim.x + threadIdx.x;
    if (i >= n4) return;
    const float4 v = ((const float4*)X)[i];
    *(__half2*)&Y[4 * i + 0] = __floats2half2_rn(v.x, v.y);
    *(__half2*)&Y[4 * i + 2] = __floats2half2_rn(v.z, v.w);
}

// transpose W[K][N] -> T[N][K], fp16
__global__ void trcvt(const float* __restrict__ W, __half* __restrict__ T, int K, int N)
{
    __shared__ float t[32][33];
    const int n = blockIdx.x * 32 + threadIdx.x;
    const int k = blockIdx.y * 32 + threadIdx.y;
    t[threadIdx.y][threadIdx.x] = W[(size_t)k * N + n];
    __syncthreads();
    const int nn = blockIdx.x * 32 + threadIdx.y;
    const int kk = blockIdx.y * 32 + threadIdx.x;
    T[(size_t)nn * K + kk] = __float2half_rn(t[threadIdx.x][threadIdx.y]);
}

// block V fp16 [m][1024] -> [mb][h][d][16m]
__global__ __launch_bounds__(512)
void vblock(const __half* __restrict__ vq, __half* __restrict__ out)
{
    __shared__ __half sh[16 * 1024];
    const int mb  = blockIdx.x;
    const int tid = threadIdx.x;

#pragma unroll
    for (int j = 0; j < 4; j++) {
        const int e  = j * 512 + tid;
        const int mm = e >> 7;
        const int c8 = e & 127;
        ((uint4*)sh)[e] = *(const uint4*)&vq[(size_t)(mb * 16 + mm) * DIM + c8 * 8];
    }
    __syncthreads();

#pragma unroll
    for (int j = 0; j < 4; j++) {
        const int e    = j * 512 + tid;
        const int pl   = e >> 7;                // head
        const int d    = (e >> 1) & 63;
        const int half = e & 1;
        __half tmp[8];
#pragma unroll
        for (int k2 = 0; k2 < 8; k2++)
            tmp[k2] = sh[(half * 8 + k2) * 1024 + pl * 64 + d];
        *(uint4*)&out[(size_t)mb * 16384 + (size_t)e * 8] = *(uint4*)tmp;
    }
}

// ===================== fp16 HMMA GEMM (cp.async double-buffered, 1 pass) ====
// EPI: 0 f32+bias, 1 f32+bias+res, 2 f32+bias+SiLU, 4 fp16 single
template <int EPI>
__global__ __launch_bounds__(256)
void gemm_mma(const __half* __restrict__ A, const __half* __restrict__ B,
              const float* __restrict__ bias, const float* __restrict__ res,
              float* __restrict__ Cf, __half* __restrict__ Cq, int M, int N, int K)
{
    extern __shared__ __half gsm[];
    const uint32_t base = smem_u32(gsm);

    const int tid  = threadIdx.x;
    const int wid  = tid >> 5, lane = tid & 31;
    const int m0   = blockIdx.y * 128, n0 = blockIdx.x * 128;
    const int wm   = (wid & 3) * 32;
    const int wn   = (wid >> 2) * 64;

    float acc[2][8][4];
#pragma unroll
    for (int i = 0; i < 2; i++)
#pragma unroll
        for (int j = 0; j < 8; j++)
#pragma unroll
            for (int r = 0; r < 4; r++) acc[i][j][r] = 0.f;

    const int la_rowA = (lane & 7) + ((lane >> 3) & 1) * 8;
    const int la_kA   = (lane >> 4) * 8;
    const int la_rowB = (lane & 7) + (lane >= 16 ? 8 : 0);
    const int la_kB   = ((lane >> 3) & 1) * 8;

    const int chunks = K >> 5;
    const int r_st  = tid >> 2;
    const int cs_st = (tid & 3) * 8;
#define G_STAGE(c, b) do { \
        const uint32_t bb = base + (uint32_t)(b) * 2 * TILE_ELEMS * 2; \
        _Pragma("unroll") \
        for (int t = 0; t < 2; t++) { \
            const int r = r_st + t * 64; \
            const uint32_t so = (uint32_t)(r * TROW + cs_st) * 2; \
            cpa16(bb + so,                  A + (size_t)(m0 + r) * K + (c) * 32 + cs_st); \
            cpa16(bb + TILE_ELEMS * 2 + so, B + (size_t)(n0 + r) * K + (c) * 32 + cs_st); \
        } \
        CP_COMMIT(); \
    } while (0)

    G_STAGE(0, 0);

    for (int c = 0; c < chunks; c++) {
        if (c + 1 < chunks) { G_STAGE(c + 1, (c + 1) & 1); CP_WAIT(1); }
        else                { CP_WAIT(0); }
        __syncthreads();

        const uint32_t bb = base + (uint32_t)(c & 1) * 2 * TILE_ELEMS * 2;
        const uint32_t aA = bb;
        const uint32_t aB = bb + TILE_ELEMS * 2;

#pragma unroll
        for (int ks = 0; ks < 32; ks += 16) {
            uint32_t af[2][4];
#pragma unroll
            for (int mt = 0; mt < 2; mt++) {
                const uint32_t off =
                    (uint32_t)((wm + mt * 16 + la_rowA) * TROW + ks + la_kA) * 2;
                ldmx4(af[mt], aA + off);
            }
#pragma unroll
            for (int nt2 = 0; nt2 < 4; nt2++) {
                uint32_t bf[4];
                const uint32_t off =
                    (uint32_t)((wn + nt2 * 16 + la_rowB) * TROW + ks + la_kB) * 2;
                ldmx4(bf, aB + off);
#pragma unroll
                for (int sub = 0; sub < 2; sub++) {
#pragma unroll
                    for (int mt = 0; mt < 2; mt++)
                        mma16816h(acc[mt][nt2 * 2 + sub], af[mt], &bf[sub * 2]);
                }
            }
        }
        __syncthreads();
    }
#undef G_STAGE

#pragma unroll
    for (int mt = 0; mt < 2; mt++) {
#pragma unroll
        for (int nt = 0; nt < 8; nt++) {
            const int row = m0 + wm + mt * 16 + (lane >> 2);
            const int col = n0 + wn + nt * 8 + (lane & 3) * 2;
#pragma unroll
            for (int half = 0; half < 2; half++) {
                const int rr = row + half * 8;
                float v0 = acc[mt][nt][half * 2 + 0] + bias[col + 0];
                float v1 = acc[mt][nt][half * 2 + 1] + bias[col + 1];
                if (EPI == 1) {
                    const float2 r2 = *(const float2*)&res[(size_t)rr * N + col];
                    v0 += r2.x; v1 += r2.y;
                }
                if (EPI == 2) {
                    v0 = v0 / (1.f + __expf(-v0));
                    v1 = v1 / (1.f + __expf(-v1));
                }
                if (EPI == 4) {
                    *(__half2*)&Cq[(size_t)rr * N + col] = __floats2half2_rn(v0, v1);
                } else {
                    *(float2*)&Cf[(size_t)rr * N + col] = make_float2(v0, v1);
                }
            }
        }
    }
}

// ===================== scores2: fp16 Q/K, 1 MMA pass ========================
__global__ __launch_bounds__(256)
void scores2(const __half* __restrict__ Q, const __half* __restrict__ K,
             __half* __restrict__ S)
{
    extern __shared__ __half ssm[];
    const uint32_t base = smem_u32(ssm);
    const uint32_t aQ  = base;
    const uint32_t aK0 = base + QTILE * 2;
    const uint32_t aK1 = base + QTILE * 4;

    const int tid  = threadIdx.x;
    const int wid  = tid >> 5, lane = tid & 31;
    const int nq0  = blockIdx.x * 128;
    const int h    = blockIdx.y;
    const int wm   = (wid & 3) * 32;
    const int wn   = (wid >> 2) * 64;

    const int r_st  = tid >> 1;
    const int c8_st = (tid & 1) * 4;

#pragma unroll
    for (int u = 0; u < 4; u++) {
        const int seg = c8_st + u;
        const uint32_t so = (uint32_t)(r_st * QROW + seg * 8) * 2;
        cpa16(aQ  + so, Q + (size_t)(nq0 + r_st) * DIM + h * 64 + seg * 8);
        cpa16(aK0 + so, K + (size_t)r_st * DIM + h * 64 + seg * 8);
    }
    CP_COMMIT();

    const int la_rowA = (lane & 7) + ((lane >> 3) & 1) * 8;
    const int la_kA   = (lane >> 4) * 8;
    const int la_rowB = (lane & 7) + (lane >= 16 ? 8 : 0);
    const int la_kB   = ((lane >> 3) & 1) * 8;

    __half* Sp = S + (size_t)h * N_TOK * N_TOK;

    for (int mb = 0; mb < 32; mb++) {
        if (mb + 1 < 32) {
            const uint32_t kb = ((mb + 1) & 1) ? aK1 : aK0;
#pragma unroll
            for (int u = 0; u < 4; u++) {
                const int seg = c8_st + u;
                const uint32_t so = (uint32_t)(r_st * QROW + seg * 8) * 2;
                cpa16(kb + so,
                      K + (size_t)((mb + 1) * 128 + r_st) * DIM + h * 64 + seg * 8);
            }
            CP_COMMIT();
            CP_WAIT(1);
        } else {
            CP_WAIT(0);
        }
        __syncthreads();

        const uint32_t aK = (mb & 1) ? aK1 : aK0;

        float acc[2][8][4];
#pragma unroll
        for (int i = 0; i < 2; i++)
#pragma unroll
            for (int j = 0; j < 8; j++)
#pragma unroll
                for (int r = 0; r < 4; r++) acc[i][j][r] = 0.f;

#pragma unroll
        for (int ks = 0; ks < 64; ks += 16) {
            uint32_t aq[2][4];
#pragma unroll
            for (int mt = 0; mt < 2; mt++) {
                const uint32_t off =
                    (uint32_t)((wm + mt * 16 + la_rowA) * QROW + ks + la_kA) * 2;
                ldmx4(aq[mt], aQ + off);
            }
#pragma unroll
            for (int nt2 = 0; nt2 < 4; nt2++) {
                uint32_t bk[4];
                const uint32_t off =
                    (uint32_t)((wn + nt2 * 16 + la_rowB) * QROW + ks + la_kB) * 2;
                ldmx4(bk, aK + off);
#pragma unroll
                for (int sub = 0; sub < 2; sub++) {
#pragma unroll
                    for (int mt = 0; mt < 2; mt++)
                        mma16816h(acc[mt][nt2 * 2 + sub], aq[mt], &bk[sub * 2]);
                }
            }
        }

#pragma unroll
        for (int mt = 0; mt < 2; mt++) {
#pragma unroll
            for (int nt = 0; nt < 8; nt++) {
                const int row = nq0 + wm + mt * 16 + (lane >> 2);
                const int col = mb * 128 + wn + nt * 8 + (lane & 3) * 2;
#pragma unroll
                for (int half = 0; half < 2; half++) {
                    *(__half2*)&Sp[(size_t)(row + half * 8) * N_TOK + col] =
                        __floats2half2_rn(acc[mt][nt][half * 2 + 0],
                                          acc[mt][nt][half * 2 + 1]);
                }
            }
        }
        __syncthreads();
    }
}

// ===================== Phase C: softmax-over-heads + PV (fp16, 1 pass) ======
// P: fp16 planes [16h][32n][24m]; V: double-buffered fp16 planes [16h][64d][40m].
// Output written directly as fp16 (A operand of the O projection).
#define P_PLANE 768                 // 32 * 24
#define V_PLANE 2560                // 64 * 40
#define V_BUF   (16 * V_PLANE)      // 40960 halves per buffer
#define PV_SMEM ((16 * P_PLANE + 2 * V_BUF) * 2)   // 188416 B

__global__ __launch_bounds__(512, 1)
void pv_mma(const __half* __restrict__ S, const __half* __restrict__ Vtb,
            __half* __restrict__ Oq)
{
    extern __shared__ __half smh[];
    __half* ps = smh;                     // 16 planes x 768
    __half* vs = smh + 16 * P_PLANE;      // 2 buffers x 16 planes x 2560

    const int tid  = threadIdx.x;
    const int wid  = tid >> 5;            // = head
    const int lane = tid & 31;
    const int n0   = blockIdx.x * 32;
    const int nn   = tid >> 4;
    const int mmq  = tid & 15;

    const uint32_t psb = smem_u32(ps);
    const uint32_t vsb = smem_u32(vs);

    float acc[2][8][4];
#pragma unroll
    for (int i = 0; i < 2; i++)
#pragma unroll
        for (int j = 0; j < 8; j++)
#pragma unroll
            for (int r = 0; r < 4; r++) acc[i][j][r] = 0.f;

    const int la_rowA = (lane & 7) + ((lane >> 3) & 1) * 8;
    const int la_kA   = (lane >> 4) * 8;
    const int la_rowB = (lane & 7) + (lane >= 16 ? 8 : 0);
    const int la_kB   = ((lane >> 3) & 1) * 8;

    const size_t N2 = (size_t)N_TOK * N_TOK;
    const __half* sp0 = S + (size_t)(n0 + nn) * N_TOK + mmq;

    // per-thread V staging geometry: 4 x 16B segments per tile
    const int ve0   = tid;                 // uint4 elems tid, tid+512, ...
#define V_STAGE(mt, buf) do { \
        const uint4* _vsrc = (const uint4*)(Vtb + (size_t)(mt) * 16384); \
        const uint32_t _vb = vsb + (uint32_t)(buf) * V_BUF * 2; \
        _Pragma("unroll") \
        for (int j = 0; j < 4; j++) { \
            const int e    = j * 512 + ve0; \
            const int pl   = e >> 7; \
            const int d    = (e >> 1) & 63; \
            const int half = e & 1; \
            cpa16(_vb + (uint32_t)(pl * V_PLANE + d * 40 + half * 8) * 2, _vsrc + e); \
        } \
        CP_COMMIT(); \
    } while (0)

    V_STAGE(0, 0);

    for (int mt0 = 0; mt0 < N_TOK / 16; mt0++) {
        const int m0 = mt0 * 16;

        // ---- softmax over heads (independent of V arrival) ----
        {
            const __half* sp = sp0 + m0;
            float sv[16];
#pragma unroll
            for (int q = 0; q < 16; q++)
                sv[q] = __half2float(sp[(size_t)q * N2]) * 0.125f;
            float mx = sv[0];
#pragma unroll
            for (int q = 1; q < 16; q++) mx = fmaxf(mx, sv[q]);
            float ssum = 0.f;
#pragma unroll
            for (int q = 0; q < 16; q++) { sv[q] = __expf(sv[q] - mx); ssum += sv[q]; }
            const float rinv = __fdividef(1.f, ssum);
#pragma unroll
            for (int q = 0; q < 16; q++)
                ps[q * P_PLANE + nn * 24 + mmq] = __float2half_rn(sv[q] * rinv);
        }

        // ---- prefetch next V tile, wait for current ----
        if (mt0 + 1 < N_TOK / 16) { V_STAGE(mt0 + 1, (mt0 + 1) & 1); CP_WAIT(1); }
        else                      { CP_WAIT(0); }
        __syncthreads();

        // ---- fp16 HMMA (1 pass) ----
        {
            const uint32_t pb = psb + (uint32_t)wid * P_PLANE * 2;
            const uint32_t vb = vsb + (uint32_t)(mt0 & 1) * V_BUF * 2
                                    + (uint32_t)wid * V_PLANE * 2;

            uint32_t ap[2][4];
#pragma unroll
            for (int mt = 0; mt < 2; mt++) {
                const uint32_t off =
                    (uint32_t)((mt * 16 + la_rowA) * 24 + la_kA) * 2;
                ldmx4(ap[mt], pb + off);
            }
#pragma unroll
            for (int nt2 = 0; nt2 < 4; nt2++) {
                uint32_t bv[4];
                const uint32_t off =
                    (uint32_t)((nt2 * 16 + la_rowB) * 40 + la_kB) * 2;
                ldmx4(bv, vb + off);
#pragma unroll
                for (int sub = 0; sub < 2; sub++) {
#pragma unroll
                    for (int mt = 0; mt < 2; mt++)
                        mma16816h(acc[mt][nt2 * 2 + sub], ap[mt], &bv[sub * 2]);
                }
            }
        }
        __syncthreads();
    }
#undef V_STAGE

    // epilogue: fp16 output (feeds the O-projection directly)
#pragma unroll
    for (int mt = 0; mt < 2; mt++) {
#pragma unroll
        for (int nt = 0; nt < 8; nt++) {
            const int row = n0 + mt * 16 + (lane >> 2);
            const int col = wid * 64 + nt * 8 + (lane & 3) * 2;
#pragma unroll
            for (int half = 0; half < 2; half++) {
                *(__half2*)&Oq[(size_t)(row + half * 8) * DIM + col] =
                    __floats2half2_rn(acc[mt][nt][half * 2 + 0],
                                      acc[mt][nt][half * 2 + 1]);
            }
        }
    }
}

// ===================== LayerNorm (dual fp32 + fp16 output) ==================
__global__ __launch_bounds__(256)
void ln_kernel(const float* __restrict__ X, const float* __restrict__ w,
               const float* __restrict__ b, float* __restrict__ out,
               __half* __restrict__ out16)
{
    const int n   = blockIdx.x;
    const int tid = threadIdx.x;
    const float4 x = ((const float4*)(X + (size_t)n * DIM))[tid];

    float s  = x.x + x.y + x.z + x.w;
    float ss = x.x * x.x + x.y * x.y + x.z * x.z + x.w * x.w;
#pragma unroll
    for (int off = 16; off; off >>= 1) {
        s  += __shfl_xor_sync(0xffffffffu, s, off);
        ss += __shfl_xor_sync(0xffffffffu, ss, off);
    }
    __shared__ float rs[8], rss[8], stat[2];
    if ((tid & 31) == 0) { rs[tid >> 5] = s; rss[tid >> 5] = ss; }
    __syncthreads();
    if (tid == 0) {
        float S = 0.f, SS = 0.f;
#pragma unroll
        for (int i = 0; i < 8; i++) { S += rs[i]; SS += rss[i]; }
        const float mean = S * (1.f / DIM);
        const float var  = SS * (1.f / DIM) - mean * mean;
        stat[0] = mean;
        stat[1] = rsqrtf(var + 1e-5f);
    }
    __syncthreads();
    const float mean = stat[0], inv = stat[1];
    const int col = tid * 4;
    const float4 wv = *(const float4*)&w[col];
    const float4 bv = *(const float4*)&b[col];
    float4 o;
    o.x = (x.x - mean) * inv * wv.x + bv.x;
    o.y = (x.y - mean) * inv * wv.y + bv.y;
    o.z = (x.z - mean) * inv * wv.z + bv.z;
    o.w = (x.w - mean) * inv * wv.w + bv.w;
    ((float4*)(out + (size_t)n * DIM))[tid] = o;
    *(__half2*)&out16[(size_t)n * DIM + col + 0] = __floats2half2_rn(o.x, o.y);
    *(__half2*)&out16[(size_t)n * DIM + col + 2] = __floats2half2_rn(o.z, o.w);
}

// ===================== coord MLP layer 2 ====================================
__global__ void mlp2_kernel(const float* __restrict__ T, const float* __restrict__ W2,
                            const float* __restrict__ b2, float* __restrict__ cw)
{
    const int warp = (blockIdx.x * blockDim.x + threadIdx.x) >> 5;
    const int lane = threadIdx.x & 31;
    if (warp >= N_TOK) return;
    const float* t = T + (size_t)warp * (DIM / 2);
    float s = 0.f;
#pragma unroll
    for (int j = 0; j < DIM / 2; j += 32) s = fmaf(t[j + lane], W2[j + lane], s);
#pragma unroll
    for (int off = 16; off; off >>= 1) s += __shfl_xor_sync(0xffffffffu, s, off);
    if (lane == 0) cw[warp] = s + b2[0];
}

// ===================== rel_pos mean =========================================
__global__ __launch_bounds__(128)
void relmean_kernel(const float* __restrict__ rel, float* __restrict__ out)
{
    const int n   = blockIdx.x;
    const int tid = threadIdx.x;
    const float* base = rel + (size_t)n * N_TOK * 3;
    float s0 = 0.f, s1 = 0.f, s2 = 0.f;
    for (int m = tid; m < N_TOK; m += 128) {
        s0 += base[m * 3 + 0];
        s1 += base[m * 3 + 1];
        s2 += base[m * 3 + 2];
    }
#pragma unroll
    for (int off = 16; off; off >>= 1) {
        s0 += __shfl_xor_sync(0xffffffffu, s0, off);
        s1 += __shfl_xor_sync(0xffffffffu, s1, off);
        s2 += __shfl_xor_sync(0xffffffffu, s2, off);
    }
    __shared__ float sm[3][4];
    if ((tid & 31) == 0) {
        sm[0][tid >> 5] = s0; sm[1][tid >> 5] = s1; sm[2][tid >> 5] = s2;
    }
    __syncthreads();
    if (tid == 0) {
        out[n * 3 + 0] = (sm[0][0] + sm[0][1] + sm[0][2] + sm[0][3]) * (1.f / N_TOK);
        out[n * 3 + 1] = (sm[1][0] + sm[1][1] + sm[1][2] + sm[1][3]) * (1.f / N_TOK);
        out[n * 3 + 2] = (sm[2][0] + sm[2][1] + sm[2][2] + sm[2][3]) * (1.f / N_TOK);
    }
}

// ===================== pos_update ===========================================
__global__ void posupd_kernel(const float* __restrict__ cw, const float* __restrict__ rm,
                              float* __restrict__ out)
{
    const int i = blockIdx.x * blockDim.x + threadIdx.x;
    if (i < N_TOK * 3) out[i] = cw[i / 3] * rm[i];
}

// ===================== launcher =============================================
extern "C" void kernel_launch(void* const* d_in, const int* in_sizes, int n_in,
                              void* d_out, int out_size)
{
    const float* h    = (const float*)d_in[0];
    const float* rel  = (const float*)d_in[1];
    const float* Wq   = (const float*)d_in[2];
    const float* bq   = (const float*)d_in[3];
    const float* Wk   = (const float*)d_in[4];
    const float* bk   = (const float*)d_in[5];
    const float* Wv   = (const float*)d_in[6];
    const float* bv   = (const float*)d_in[7];
    const float* Wo   = (const float*)d_in[8];
    const float* bo   = (const float*)d_in[9];
    const float* W1   = (const float*)d_in[10];
    const float* b1   = (const float*)d_in[11];
    const float* W2   = (const float*)d_in[12];
    const float* b2   = (const float*)d_in[13];
    const float* lnw  = (const float*)d_in[14];
    const float* lnb  = (const float*)d_in[15];
    float* out = (float*)d_out;

    float *x, *t, *cw, *rm;
    __half *s, *aq, *qq, *kq, *vq, *vtb;
    __half *wq16, *wk16, *wv16, *wo16, *w116;
    cudaGetSymbolAddress((void**)&x,    g_x);
    cudaGetSymbolAddress((void**)&t,    g_t);
    cudaGetSymbolAddress((void**)&cw,   g_cw);
    cudaGetSymbolAddress((void**)&rm,   g_relmean);
    cudaGetSymbolAddress((void**)&s,    g_s);
    cudaGetSymbolAddress((void**)&aq,   g_aq);
    cudaGetSymbolAddress((void**)&qq,   g_qq);
    cudaGetSymbolAddress((void**)&kq,   g_kq);
    cudaGetSymbolAddress((void**)&vq,   g_vq);
    cudaGetSymbolAddress((void**)&vtb,  g_vtb);
    cudaGetSymbolAddress((void**)&wq16, g_wq16);
    cudaGetSymbolAddress((void**)&wk16, g_wk16);
    cudaGetSymbolAddress((void**)&wv16, g_wv16);
    cudaGetSymbolAddress((void**)&wo16, g_wo16);
    cudaGetSymbolAddress((void**)&w116, g_w116);

    cudaFuncSetAttribute(pv_mma,      cudaFuncAttributeMaxDynamicSharedMemorySize, PV_SMEM);
    cudaFuncSetAttribute(scores2,     cudaFuncAttributeMaxDynamicSharedMemorySize, SC_SMEM);
    cudaFuncSetAttribute(gemm_mma<1>, cudaFuncAttributeMaxDynamicSharedMemorySize, GEMM_SMEM);
    cudaFuncSetAttribute(gemm_mma<2>, cudaFuncAttributeMaxDynamicSharedMemorySize, GEMM_SMEM);
    cudaFuncSetAttribute(gemm_mma<4>, cudaFuncAttributeMaxDynamicSharedMemorySize, GEMM_SMEM);

    // independent: rel_pos mean
    relmean_kernel<<<N_TOK, 128>>>(rel, rm);

    // weight prep: transpose + fp16 convert
    trcvt<<<dim3(32, 32), dim3(32, 32)>>>(Wq, wq16, DIM, DIM);
    trcvt<<<dim3(32, 32), dim3(32, 32)>>>(Wk, wk16, DIM, DIM);
    trcvt<<<dim3(32, 32), dim3(32, 32)>>>(Wv, wv16, DIM, DIM);
    trcvt<<<dim3(32, 32), dim3(32, 32)>>>(Wo, wo16, DIM, DIM);
    trcvt<<<dim3(16, 32), dim3(32, 32)>>>(W1, w116, DIM, DIM / 2);

    // h -> fp16 A operand
    cvt16<<<(N_TOK * DIM / 4 + 255) / 256, 256>>>(h, aq, N_TOK * DIM / 4);

    // QKV: all fp16 single-plane, 1-pass
    gemm_mma<4><<<dim3(8, 32), 256, GEMM_SMEM>>>(aq, wq16, bq, nullptr, nullptr, qq, N_TOK, DIM, DIM);
    gemm_mma<4><<<dim3(8, 32), 256, GEMM_SMEM>>>(aq, wk16, bk, nullptr, nullptr, kq, N_TOK, DIM, DIM);
    gemm_mma<4><<<dim3(8, 32), 256, GEMM_SMEM>>>(aq, wv16, bv, nullptr, nullptr, vq, N_TOK, DIM, DIM);

    // block V for pv_mma staging
    vblock<<<N_TOK / 16, 512>>>(vq, vtb);

    // attention phase A: raw scores -> fp16 (1-pass fp16 MMA)
    scores2<<<dim3(32, 16), 256, SC_SMEM>>>(qq, kq, s);

    // attention phase C: softmax + PV, writes fp16 O-proj A operand directly
    pv_mma<<<N_TOK / 32, 512, PV_SMEM>>>(s, vtb, aq);

    // O projection + residual (fp16 A already in aq)
    gemm_mma<1><<<dim3(8, 32), 256, GEMM_SMEM>>>(aq, wo16, bo, h, x, nullptr, N_TOK, DIM, DIM);

    // layernorm -> hn (fp32 output) + fp16 copy for W1 GEMM
    ln_kernel<<<N_TOK, 256>>>(x, lnw, lnb, out, aq);

    // coord MLP
    gemm_mma<2><<<dim3(4, 32), 256, GEMM_SMEM>>>(aq, w116, b1, nullptr, t, nullptr, N_TOK, DIM / 2, DIM);
    mlp2_kernel<<<(N_TOK * 32) / 256, 256>>>(t, W2, b2, cw);

    // pos_update
    posupd_kernel<<<(N_TOK * 3 + 255) / 256, 256>>>(cw, rm, out + (size_t)N_TOK * DIM);
}